// round 6
// baseline (speedup 1.0000x reference)
#include <cuda_runtime.h>
#include <math.h>

// Problem constants
#define NN   50000
#define DD   128
#define MM   800000
#define EE   32
#define KIN  160    // D + E
#define MSGD 128

// Edge kernel tiling
#define TE   64
#define EIS  164    // padded stride for edge-input tile (160 -> 164)
#define HS   260    // padded stride for hidden tile   (256 -> 260)

// GRU kernel tiling
#define TN   32
#define XS   132
#define GS   388

// Scratch (allocation-free rule: __device__ globals)
__device__ float g_msgsum[(size_t)NN * DD];
__device__ float g_bufA[(size_t)NN * DD];
__device__ float g_bufB[(size_t)NN * DD];

__device__ __forceinline__ float sigf(float x) { return 1.0f / (1.0f + expf(-x)); }

// ---------------------------------------------------------------------------
__global__ void copy_relu_kernel(const float* __restrict__ src, float* __restrict__ dst,
                                 int n, int do_relu) {
    int i = blockIdx.x * blockDim.x + threadIdx.x;
    if (i < n) {
        float v = src[i];
        dst[i] = do_relu ? fmaxf(v, 0.0f) : v;
    }
}

// ---------------------------------------------------------------------------
// Fused edge kernel: gather -> H = relu(EI @ [W1|A1] + b) ->
// msg = (H1@W2+b2) * sigmoid(HA@A2+ab2) -> atomic scatter-add into msum[dst].
// One block = 64 edges, 256 threads.
// ---------------------------------------------------------------------------
__global__ void __launch_bounds__(256)
edge_kernel(const float* __restrict__ state,
            const int*   __restrict__ eidx,
            const float* __restrict__ efeat,
            const float* __restrict__ W1p, const float* __restrict__ b1p,
            const float* __restrict__ W2p, const float* __restrict__ b2p,
            const float* __restrict__ A1p, const float* __restrict__ ab1p,
            const float* __restrict__ A2p, const float* __restrict__ ab2p,
            float* __restrict__ msum)
{
    extern __shared__ float sm[];
    float* s_ei = sm;              // TE * EIS
    float* s_h  = sm + TE * EIS;   // TE * HS
    __shared__ int s_src[TE];
    __shared__ int s_dst[TE];

    const int tid = threadIdx.x;
    const int m0  = blockIdx.x * TE;

    if (tid < TE) {
        int m = m0 + tid;
        s_src[tid] = (m < MM) ? eidx[m] : 0;
        s_dst[tid] = (m < MM) ? eidx[MM + m] : 0;
    }
    __syncthreads();

    // Gather diff part: 64 edges x 32 float4
    for (int t = tid; t < TE * 32; t += 256) {
        int e = t >> 5, q = t & 31;
        const float4 a = ((const float4*)(state + (size_t)s_src[e] * DD))[q];
        const float4 b = ((const float4*)(state + (size_t)s_dst[e] * DD))[q];
        float4 v; v.x = a.x - b.x; v.y = a.y - b.y; v.z = a.z - b.z; v.w = a.w - b.w;
        *(float4*)(s_ei + e * EIS + q * 4) = v;
    }
    // Edge features: 64 edges x 8 float4
    for (int t = tid; t < TE * 8; t += 256) {
        int e = t >> 3, q = t & 7;
        int m = m0 + e;
        float4 v = make_float4(0.f, 0.f, 0.f, 0.f);
        if (m < MM) v = ((const float4*)(efeat + (size_t)m * EE))[q];
        *(float4*)(s_ei + e * EIS + DD + q * 4) = v;
    }
    __syncthreads();

    const int cg = tid & 15;     // 16 col groups
    const int rg = tid >> 4;     // 16 row groups
    const int cb = cg * 8;
    const int rb = rg * 4;

    // ---- GEMM1: hidden = relu(EI @ W + b), two halves ----
    #pragma unroll
    for (int half = 0; half < 2; half++) {
        const float* Wp = half ? A1p : W1p;
        const float* bp = half ? ab1p : b1p;
        float acc[4][8];
        #pragma unroll
        for (int i = 0; i < 4; i++)
            #pragma unroll
            for (int j = 0; j < 8; j++) acc[i][j] = 0.0f;

        #pragma unroll 4
        for (int k = 0; k < KIN; k++) {
            const float4 w0 = *(const float4*)(Wp + k * MSGD + cb);
            const float4 w1 = *(const float4*)(Wp + k * MSGD + cb + 4);
            float ev[4];
            #pragma unroll
            for (int i = 0; i < 4; i++) ev[i] = s_ei[(rb + i) * EIS + k];
            #pragma unroll
            for (int i = 0; i < 4; i++) {
                acc[i][0] += ev[i] * w0.x; acc[i][1] += ev[i] * w0.y;
                acc[i][2] += ev[i] * w0.z; acc[i][3] += ev[i] * w0.w;
                acc[i][4] += ev[i] * w1.x; acc[i][5] += ev[i] * w1.y;
                acc[i][6] += ev[i] * w1.z; acc[i][7] += ev[i] * w1.w;
            }
        }
        #pragma unroll
        for (int i = 0; i < 4; i++)
            #pragma unroll
            for (int j = 0; j < 8; j++) {
                float v = acc[i][j] + bp[cb + j];
                s_h[(rb + i) * HS + half * MSGD + cb + j] = fmaxf(v, 0.0f);
            }
    }
    __syncthreads();

    // ---- GEMM2 split into two sequential halves (halves L1 wavefront load) ----
    float am[4][8];
    #pragma unroll
    for (int half = 0; half < 2; half++) {
        const float* Wp = half ? A2p : W2p;
        float acc[4][8];
        #pragma unroll
        for (int i = 0; i < 4; i++)
            #pragma unroll
            for (int j = 0; j < 8; j++) acc[i][j] = 0.0f;

        #pragma unroll 4
        for (int k = 0; k < MSGD; k++) {
            const float4 w0 = *(const float4*)(Wp + k * MSGD + cb);
            const float4 w1 = *(const float4*)(Wp + k * MSGD + cb + 4);
            float hv[4];
            #pragma unroll
            for (int i = 0; i < 4; i++)
                hv[i] = s_h[(rb + i) * HS + half * MSGD + k];
            #pragma unroll
            for (int i = 0; i < 4; i++) {
                acc[i][0] += hv[i] * w0.x; acc[i][1] += hv[i] * w0.y;
                acc[i][2] += hv[i] * w0.z; acc[i][3] += hv[i] * w0.w;
                acc[i][4] += hv[i] * w1.x; acc[i][5] += hv[i] * w1.y;
                acc[i][6] += hv[i] * w1.z; acc[i][7] += hv[i] * w1.w;
            }
        }
        if (half == 0) {
            #pragma unroll
            for (int i = 0; i < 4; i++)
                #pragma unroll
                for (int j = 0; j < 8; j++)
                    am[i][j] = acc[i][j] + b2p[cb + j];
        } else {
            // gate + atomic scatter-add
            #pragma unroll
            for (int i = 0; i < 4; i++) {
                int m = m0 + rb + i;
                if (m >= MM) continue;
                float* dp = msum + (size_t)s_dst[rb + i] * DD + cb;
                #pragma unroll
                for (int j = 0; j < 8; j++) {
                    float av = acc[i][j] + ab2p[cb + j];
                    atomicAdd(dp + j, am[i][j] * sigf(av));
                }
            }
        }
    }
}

// ---------------------------------------------------------------------------
// Fused GRU kernel: per 32-node tile. 256 threads.
// ---------------------------------------------------------------------------
__global__ void __launch_bounds__(256)
gru_kernel(const float* __restrict__ xmsg, const float* __restrict__ hstate,
           const float* __restrict__ Wih, const float* __restrict__ bih,
           const float* __restrict__ Whh, const float* __restrict__ bhh,
           float* __restrict__ out)
{
    extern __shared__ float sm[];
    float* s_x  = sm;                        // TN * XS
    float* s_h  = s_x + TN * XS;             // TN * XS
    float* s_gi = s_h + TN * XS;             // TN * GS
    float* s_gh = s_gi + TN * GS;            // TN * GS

    const int tid = threadIdx.x;
    const int n0  = blockIdx.x * TN;

    for (int t = tid; t < TN * 32; t += 256) {
        int r = t >> 5, q = t & 31;
        int node = n0 + r;
        float4 vx = make_float4(0.f, 0.f, 0.f, 0.f);
        float4 vh = vx;
        if (node < NN) {
            vx = ((const float4*)(xmsg   + (size_t)node * DD))[q];
            vh = ((const float4*)(hstate + (size_t)node * DD))[q];
        }
        *(float4*)(s_x + r * XS + q * 4) = vx;
        *(float4*)(s_h + r * XS + q * 4) = vh;
    }
    __syncthreads();

    const int lane = tid & 31;
    const int wg   = tid >> 5;     // 8 row groups
    const int rb   = wg * 4;
    const int cb   = lane * 12;    // 32*12 = 384 cols

    #pragma unroll
    for (int pass = 0; pass < 2; pass++) {
        const float* xs = pass ? s_h : s_x;
        const float* Wp = pass ? Whh : Wih;
        const float* bp = pass ? bhh : bih;
        float* gout     = pass ? s_gh : s_gi;

        float acc[4][12];
        #pragma unroll
        for (int i = 0; i < 4; i++)
            #pragma unroll
            for (int j = 0; j < 12; j++) acc[i][j] = 0.0f;

        #pragma unroll 2
        for (int k = 0; k < DD; k++) {
            const float4 w0 = *(const float4*)(Wp + k * 384 + cb);
            const float4 w1 = *(const float4*)(Wp + k * 384 + cb + 4);
            const float4 w2 = *(const float4*)(Wp + k * 384 + cb + 8);
            float xv[4];
            #pragma unroll
            for (int i = 0; i < 4; i++) xv[i] = xs[(rb + i) * XS + k];
            #pragma unroll
            for (int i = 0; i < 4; i++) {
                acc[i][0]  += xv[i] * w0.x; acc[i][1]  += xv[i] * w0.y;
                acc[i][2]  += xv[i] * w0.z; acc[i][3]  += xv[i] * w0.w;
                acc[i][4]  += xv[i] * w1.x; acc[i][5]  += xv[i] * w1.y;
                acc[i][6]  += xv[i] * w1.z; acc[i][7]  += xv[i] * w1.w;
                acc[i][8]  += xv[i] * w2.x; acc[i][9]  += xv[i] * w2.y;
                acc[i][10] += xv[i] * w2.z; acc[i][11] += xv[i] * w2.w;
            }
        }
        #pragma unroll
        for (int i = 0; i < 4; i++)
            #pragma unroll
            for (int j = 0; j < 12; j++)
                gout[(rb + i) * GS + cb + j] = acc[i][j] + bp[cb + j];
        __syncthreads();
    }

    for (int t = tid; t < TN * DD; t += 256) {
        int r = t >> 7, j = t & 127;
        int node = n0 + r;
        if (node >= NN) continue;
        float gir = s_gi[r * GS + j];
        float giz = s_gi[r * GS + 128 + j];
        float gin = s_gi[r * GS + 256 + j];
        float ghr = s_gh[r * GS + j];
        float ghz = s_gh[r * GS + 128 + j];
        float ghn = s_gh[r * GS + 256 + j];
        float h   = s_h[r * XS + j];
        float rr  = sigf(gir + ghr);
        float zz  = sigf(giz + ghz);
        float nn  = tanhf(gin + rr * ghn);
        out[(size_t)node * DD + j] = (1.0f - zz) * nn + zz * h;
    }
}

// ---------------------------------------------------------------------------
extern "C" void kernel_launch(void* const* d_in, const int* in_sizes, int n_in,
                              void* d_out, int out_size) {
    const float* node_feat = (const float*)d_in[0];
    const int*   edge_index = (const int*)d_in[1];
    const float* edge_feat = (const float*)d_in[2];
    const float* W1  = (const float*)d_in[3];
    const float* b1  = (const float*)d_in[4];
    const float* W2  = (const float*)d_in[5];
    const float* b2  = (const float*)d_in[6];
    const float* A1  = (const float*)d_in[7];
    const float* ab1 = (const float*)d_in[8];
    const float* A2  = (const float*)d_in[9];
    const float* ab2 = (const float*)d_in[10];
    const float* Wih = (const float*)d_in[11];
    const float* bih = (const float*)d_in[12];
    const float* Whh = (const float*)d_in[13];
    const float* bhh = (const float*)d_in[14];

    float *msum, *bufA, *bufB;
    cudaGetSymbolAddress((void**)&msum, g_msgsum);
    cudaGetSymbolAddress((void**)&bufA, g_bufA);
    cudaGetSymbolAddress((void**)&bufB, g_bufB);

    const int EDGE_SMEM = (TE * EIS + TE * HS) * (int)sizeof(float);         // ~108.5 KB
    const int GRU_SMEM  = (2 * TN * XS + 2 * TN * GS) * (int)sizeof(float);  // ~130 KB
    cudaFuncSetAttribute(edge_kernel, cudaFuncAttributeMaxDynamicSharedMemorySize, EDGE_SMEM);
    cudaFuncSetAttribute(gru_kernel,  cudaFuncAttributeMaxDynamicSharedMemorySize, GRU_SMEM);

    const int nElems = NN * DD;

    copy_relu_kernel<<<(nElems + 255) / 256, 256>>>(node_feat, bufA, nElems, 0);

    float* cur = bufA;
    float* nxt = bufB;

    for (int step = 0; step < 4; step++) {
        int ii = step >> 1;

        if (step == 2) {
            copy_relu_kernel<<<(nElems + 255) / 256, 256>>>(cur, cur, nElems, 1);
        }

        cudaMemsetAsync(msum, 0, sizeof(float) * (size_t)nElems);

        edge_kernel<<<MM / TE, 256, EDGE_SMEM>>>(
            cur, edge_index, edge_feat,
            W1 + (size_t)ii * KIN * MSGD,  b1  + (size_t)ii * MSGD,
            W2 + (size_t)ii * MSGD * MSGD, b2  + (size_t)ii * MSGD,
            A1 + (size_t)ii * KIN * MSGD,  ab1 + (size_t)ii * MSGD,
            A2 + (size_t)ii * MSGD * MSGD, ab2 + (size_t)ii * MSGD,
            msum);

        float* outp = (step == 3) ? (float*)d_out : nxt;

        gru_kernel<<<(NN + TN - 1) / TN, 256, GRU_SMEM>>>(
            msum, cur,
            Wih + (size_t)ii * MSGD * 384, bih + (size_t)ii * 384,
            Whh + (size_t)ii * DD * 384,   bhh + (size_t)ii * 384,
            outp);

        if (step < 3) { float* t = cur; cur = nxt; nxt = t; }
    }
}

// round 7
// speedup vs baseline: 1.0945x; 1.0945x over previous
#include <cuda_runtime.h>
#include <math.h>

// Problem constants
#define NN   50000
#define DD   128
#define MM   800000
#define EE   32
#define KIN  160    // D + E
#define MSGD 128

// Edge kernel tiling: 64 edges/block, 128 threads, 8x8 tile per thread
#define TE   64
#define EIS  164    // padded stride for edge-input tile
#define HS   260    // padded stride for hidden tile

// GRU kernel tiling
#define TN   32
#define XS   132
#define GS   388

typedef unsigned long long u64;

// Scratch (allocation-free rule: __device__ globals)
__device__ float g_msgsum[(size_t)NN * DD];
__device__ float g_bufA[(size_t)NN * DD];
__device__ float g_bufB[(size_t)NN * DD];

__device__ __forceinline__ float sigf(float x) { return 1.0f / (1.0f + expf(-x)); }

// ---- packed f32x2 helpers (PTX-only path; bit-identical to 2x scalar FFMA) ----
__device__ __forceinline__ u64 pack2(float x) {
    u64 r;
    asm("mov.b64 %0, {%1, %1};" : "=l"(r) : "r"(__float_as_uint(x)));
    return r;
}
__device__ __forceinline__ void ffma2(u64& d, u64 a, u64 b) {
    asm("fma.rn.f32x2 %0, %1, %2, %0;" : "+l"(d) : "l"(a), "l"(b));
}
__device__ __forceinline__ u64 add2(u64 a, u64 b) {
    u64 d;
    asm("add.rn.f32x2 %0, %1, %2;" : "=l"(d) : "l"(a), "l"(b));
    return d;
}
__device__ __forceinline__ void unpack2(u64 v, float& lo, float& hi) {
    unsigned int a, b;
    asm("mov.b64 {%0, %1}, %2;" : "=r"(a), "=r"(b) : "l"(v));
    lo = __uint_as_float(a); hi = __uint_as_float(b);
}

// ---------------------------------------------------------------------------
__global__ void copy_relu_kernel(const float* __restrict__ src, float* __restrict__ dst,
                                 int n, int do_relu) {
    int i = blockIdx.x * blockDim.x + threadIdx.x;
    if (i < n) {
        float v = src[i];
        dst[i] = do_relu ? fmaxf(v, 0.0f) : v;
    }
}

// ---------------------------------------------------------------------------
// Fused edge kernel: gather -> H = relu(EI @ [W1|A1] + b) ->
// msg = (H1@W2+b2) * sigmoid(HA@A2+ab2) -> atomic scatter-add into msum[dst].
// 64 edges/block, 128 threads, per-thread 8 rows x 8 cols with f32x2 FMA.
// ---------------------------------------------------------------------------
__global__ void __launch_bounds__(128, 2)
edge_kernel(const float* __restrict__ state,
            const int*   __restrict__ eidx,
            const float* __restrict__ efeat,
            const float* __restrict__ W1p, const float* __restrict__ b1p,
            const float* __restrict__ W2p, const float* __restrict__ b2p,
            const float* __restrict__ A1p, const float* __restrict__ ab1p,
            const float* __restrict__ A2p, const float* __restrict__ ab2p,
            float* __restrict__ msum)
{
    extern __shared__ float sm[];
    float* s_ei = sm;              // TE * EIS
    float* s_h  = sm + TE * EIS;   // TE * HS
    __shared__ int s_src[TE];
    __shared__ int s_dst[TE];

    const int tid = threadIdx.x;
    const int m0  = blockIdx.x * TE;

    if (tid < TE) {
        int m = m0 + tid;
        s_src[tid] = (m < MM) ? eidx[m] : 0;
        s_dst[tid] = (m < MM) ? eidx[MM + m] : 0;
    }
    __syncthreads();

    // Gather diff part: 64 edges x 32 float4
    for (int t = tid; t < TE * 32; t += 128) {
        int e = t >> 5, q = t & 31;
        const float4 a = ((const float4*)(state + (size_t)s_src[e] * DD))[q];
        const float4 b = ((const float4*)(state + (size_t)s_dst[e] * DD))[q];
        float4 v; v.x = a.x - b.x; v.y = a.y - b.y; v.z = a.z - b.z; v.w = a.w - b.w;
        *(float4*)(s_ei + e * EIS + q * 4) = v;
    }
    // Edge features: 64 edges x 8 float4
    for (int t = tid; t < TE * 8; t += 128) {
        int e = t >> 3, q = t & 7;
        int m = m0 + e;
        float4 v = make_float4(0.f, 0.f, 0.f, 0.f);
        if (m < MM) v = ((const float4*)(efeat + (size_t)m * EE))[q];
        *(float4*)(s_ei + e * EIS + DD + q * 4) = v;
    }
    __syncthreads();

    const int cg = tid & 15;     // 16 col groups x 8 cols = 128 cols
    const int rg = tid >> 4;     // 8 row groups  x 8 rows = 64 rows
    const int cb = cg * 8;
    const int rb = rg * 8;

    // ---- GEMM1: hidden = relu(EI @ W + b), two halves (msg / att nets) ----
    #pragma unroll
    for (int half = 0; half < 2; half++) {
        const float* Wp = half ? A1p : W1p;
        const float* bp = half ? ab1p : b1p;
        u64 acc[8][4];
        #pragma unroll
        for (int i = 0; i < 8; i++)
            #pragma unroll
            for (int j = 0; j < 4; j++) acc[i][j] = 0ull;

        #pragma unroll 2
        for (int k = 0; k < KIN; k++) {
            const ulonglong2 wlo = *(const ulonglong2*)(Wp + k * MSGD + cb);
            const ulonglong2 whi = *(const ulonglong2*)(Wp + k * MSGD + cb + 4);
            #pragma unroll
            for (int i = 0; i < 8; i++) {
                u64 ev = pack2(s_ei[(rb + i) * EIS + k]);
                ffma2(acc[i][0], ev, wlo.x);
                ffma2(acc[i][1], ev, wlo.y);
                ffma2(acc[i][2], ev, whi.x);
                ffma2(acc[i][3], ev, whi.y);
            }
        }
        const float4 blo = *(const float4*)(bp + cb);
        const float4 bhi = *(const float4*)(bp + cb + 4);
        #pragma unroll
        for (int i = 0; i < 8; i++) {
            float v0, v1, v2, v3, v4, v5, v6, v7;
            unpack2(acc[i][0], v0, v1);
            unpack2(acc[i][1], v2, v3);
            unpack2(acc[i][2], v4, v5);
            unpack2(acc[i][3], v6, v7);
            float4 o0, o1;
            o0.x = fmaxf(v0 + blo.x, 0.f); o0.y = fmaxf(v1 + blo.y, 0.f);
            o0.z = fmaxf(v2 + blo.z, 0.f); o0.w = fmaxf(v3 + blo.w, 0.f);
            o1.x = fmaxf(v4 + bhi.x, 0.f); o1.y = fmaxf(v5 + bhi.y, 0.f);
            o1.z = fmaxf(v6 + bhi.z, 0.f); o1.w = fmaxf(v7 + bhi.w, 0.f);
            *(float4*)(s_h + (rb + i) * HS + half * MSGD + cb)     = o0;
            *(float4*)(s_h + (rb + i) * HS + half * MSGD + cb + 4) = o1;
        }
    }
    __syncthreads();

    // ---- GEMM2: msg half then att half; keep msg result packed in regs ----
    u64 msave[8][4];
    #pragma unroll
    for (int half = 0; half < 2; half++) {
        const float* Wp = half ? A2p : W2p;
        u64 acc[8][4];
        #pragma unroll
        for (int i = 0; i < 8; i++)
            #pragma unroll
            for (int j = 0; j < 4; j++) acc[i][j] = 0ull;

        #pragma unroll 2
        for (int k = 0; k < MSGD; k++) {
            const ulonglong2 wlo = *(const ulonglong2*)(Wp + k * MSGD + cb);
            const ulonglong2 whi = *(const ulonglong2*)(Wp + k * MSGD + cb + 4);
            #pragma unroll
            for (int i = 0; i < 8; i++) {
                u64 hv = pack2(s_h[(rb + i) * HS + half * MSGD + k]);
                ffma2(acc[i][0], hv, wlo.x);
                ffma2(acc[i][1], hv, wlo.y);
                ffma2(acc[i][2], hv, whi.x);
                ffma2(acc[i][3], hv, whi.y);
            }
        }
        if (half == 0) {
            const ulonglong2 b2lo = *(const ulonglong2*)(b2p + cb);
            const ulonglong2 b2hi = *(const ulonglong2*)(b2p + cb + 4);
            #pragma unroll
            for (int i = 0; i < 8; i++) {
                msave[i][0] = add2(acc[i][0], b2lo.x);
                msave[i][1] = add2(acc[i][1], b2lo.y);
                msave[i][2] = add2(acc[i][2], b2hi.x);
                msave[i][3] = add2(acc[i][3], b2hi.y);
            }
        } else {
            const float4 ablo = *(const float4*)(ab2p + cb);
            const float4 abhi = *(const float4*)(ab2p + cb + 4);
            #pragma unroll
            for (int i = 0; i < 8; i++) {
                float* dp = msum + (size_t)s_dst[rb + i] * DD + cb;
                float a0, a1, a2, a3, a4, a5, a6, a7;
                unpack2(acc[i][0], a0, a1);
                unpack2(acc[i][1], a2, a3);
                unpack2(acc[i][2], a4, a5);
                unpack2(acc[i][3], a6, a7);
                float m0v, m1v, m2v, m3v, m4v, m5v, m6v, m7v;
                unpack2(msave[i][0], m0v, m1v);
                unpack2(msave[i][1], m2v, m3v);
                unpack2(msave[i][2], m4v, m5v);
                unpack2(msave[i][3], m6v, m7v);
                atomicAdd(dp + 0, m0v * sigf(a0 + ablo.x));
                atomicAdd(dp + 1, m1v * sigf(a1 + ablo.y));
                atomicAdd(dp + 2, m2v * sigf(a2 + ablo.z));
                atomicAdd(dp + 3, m3v * sigf(a3 + ablo.w));
                atomicAdd(dp + 4, m4v * sigf(a4 + abhi.x));
                atomicAdd(dp + 5, m5v * sigf(a5 + abhi.y));
                atomicAdd(dp + 6, m6v * sigf(a6 + abhi.z));
                atomicAdd(dp + 7, m7v * sigf(a7 + abhi.w));
            }
        }
    }
}

// ---------------------------------------------------------------------------
// Fused GRU kernel: per 32-node tile, 256 threads, f32x2 inner loops.
// ---------------------------------------------------------------------------
__global__ void __launch_bounds__(256)
gru_kernel(const float* __restrict__ xmsg, const float* __restrict__ hstate,
           const float* __restrict__ Wih, const float* __restrict__ bih,
           const float* __restrict__ Whh, const float* __restrict__ bhh,
           float* __restrict__ out)
{
    extern __shared__ float sm[];
    float* s_x  = sm;                        // TN * XS
    float* s_h  = s_x + TN * XS;             // TN * XS
    float* s_gi = s_h + TN * XS;             // TN * GS
    float* s_gh = s_gi + TN * GS;            // TN * GS

    const int tid = threadIdx.x;
    const int n0  = blockIdx.x * TN;

    for (int t = tid; t < TN * 32; t += 256) {
        int r = t >> 5, q = t & 31;
        int node = n0 + r;
        float4 vx = make_float4(0.f, 0.f, 0.f, 0.f);
        float4 vh = vx;
        if (node < NN) {
            vx = ((const float4*)(xmsg   + (size_t)node * DD))[q];
            vh = ((const float4*)(hstate + (size_t)node * DD))[q];
        }
        *(float4*)(s_x + r * XS + q * 4) = vx;
        *(float4*)(s_h + r * XS + q * 4) = vh;
    }
    __syncthreads();

    const int lane = tid & 31;
    const int wg   = tid >> 5;     // 8 row groups
    const int rb   = wg * 4;
    const int cb   = lane * 12;    // 32*12 = 384 cols

    #pragma unroll
    for (int pass = 0; pass < 2; pass++) {
        const float* xs = pass ? s_h : s_x;
        const float* Wp = pass ? Whh : Wih;
        const float* bp = pass ? bhh : bih;
        float* gout     = pass ? s_gh : s_gi;

        u64 acc[4][6];
        #pragma unroll
        for (int i = 0; i < 4; i++)
            #pragma unroll
            for (int j = 0; j < 6; j++) acc[i][j] = 0ull;

        #pragma unroll 2
        for (int k = 0; k < DD; k++) {
            const ulonglong2 w0 = *(const ulonglong2*)(Wp + k * 384 + cb);
            const ulonglong2 w1 = *(const ulonglong2*)(Wp + k * 384 + cb + 4);
            const ulonglong2 w2 = *(const ulonglong2*)(Wp + k * 384 + cb + 8);
            #pragma unroll
            for (int i = 0; i < 4; i++) {
                u64 xv = pack2(xs[(rb + i) * XS + k]);
                ffma2(acc[i][0], xv, w0.x);
                ffma2(acc[i][1], xv, w0.y);
                ffma2(acc[i][2], xv, w1.x);
                ffma2(acc[i][3], xv, w1.y);
                ffma2(acc[i][4], xv, w2.x);
                ffma2(acc[i][5], xv, w2.y);
            }
        }
        #pragma unroll
        for (int i = 0; i < 4; i++) {
            #pragma unroll
            for (int j = 0; j < 6; j++) {
                float lo, hi;
                unpack2(acc[i][j], lo, hi);
                gout[(rb + i) * GS + cb + 2 * j]     = lo + bp[cb + 2 * j];
                gout[(rb + i) * GS + cb + 2 * j + 1] = hi + bp[cb + 2 * j + 1];
            }
        }
        __syncthreads();
    }

    for (int t = tid; t < TN * DD; t += 256) {
        int r = t >> 7, j = t & 127;
        int node = n0 + r;
        if (node >= NN) continue;
        float gir = s_gi[r * GS + j];
        float giz = s_gi[r * GS + 128 + j];
        float gin = s_gi[r * GS + 256 + j];
        float ghr = s_gh[r * GS + j];
        float ghz = s_gh[r * GS + 128 + j];
        float ghn = s_gh[r * GS + 256 + j];
        float h   = s_h[r * XS + j];
        float rr  = sigf(gir + ghr);
        float zz  = sigf(giz + ghz);
        float nn  = tanhf(gin + rr * ghn);
        out[(size_t)node * DD + j] = (1.0f - zz) * nn + zz * h;
    }
}

// ---------------------------------------------------------------------------
extern "C" void kernel_launch(void* const* d_in, const int* in_sizes, int n_in,
                              void* d_out, int out_size) {
    const float* node_feat = (const float*)d_in[0];
    const int*   edge_index = (const int*)d_in[1];
    const float* edge_feat = (const float*)d_in[2];
    const float* W1  = (const float*)d_in[3];
    const float* b1  = (const float*)d_in[4];
    const float* W2  = (const float*)d_in[5];
    const float* b2  = (const float*)d_in[6];
    const float* A1  = (const float*)d_in[7];
    const float* ab1 = (const float*)d_in[8];
    const float* A2  = (const float*)d_in[9];
    const float* ab2 = (const float*)d_in[10];
    const float* Wih = (const float*)d_in[11];
    const float* bih = (const float*)d_in[12];
    const float* Whh = (const float*)d_in[13];
    const float* bhh = (const float*)d_in[14];

    float *msum, *bufA, *bufB;
    cudaGetSymbolAddress((void**)&msum, g_msgsum);
    cudaGetSymbolAddress((void**)&bufA, g_bufA);
    cudaGetSymbolAddress((void**)&bufB, g_bufB);

    const int EDGE_SMEM = (TE * EIS + TE * HS) * (int)sizeof(float);         // ~108.5 KB
    const int GRU_SMEM  = (2 * TN * XS + 2 * TN * GS) * (int)sizeof(float);  // ~130 KB
    cudaFuncSetAttribute(edge_kernel, cudaFuncAttributeMaxDynamicSharedMemorySize, EDGE_SMEM);
    cudaFuncSetAttribute(gru_kernel,  cudaFuncAttributeMaxDynamicSharedMemorySize, GRU_SMEM);

    const int nElems = NN * DD;

    copy_relu_kernel<<<(nElems + 255) / 256, 256>>>(node_feat, bufA, nElems, 0);

    float* cur = bufA;
    float* nxt = bufB;

    for (int step = 0; step < 4; step++) {
        int ii = step >> 1;

        if (step == 2) {
            copy_relu_kernel<<<(nElems + 255) / 256, 256>>>(cur, cur, nElems, 1);
        }

        cudaMemsetAsync(msum, 0, sizeof(float) * (size_t)nElems);

        edge_kernel<<<MM / TE, 128, EDGE_SMEM>>>(
            cur, edge_index, edge_feat,
            W1 + (size_t)ii * KIN * MSGD,  b1  + (size_t)ii * MSGD,
            W2 + (size_t)ii * MSGD * MSGD, b2  + (size_t)ii * MSGD,
            A1 + (size_t)ii * KIN * MSGD,  ab1 + (size_t)ii * MSGD,
            A2 + (size_t)ii * MSGD * MSGD, ab2 + (size_t)ii * MSGD,
            msum);

        float* outp = (step == 3) ? (float*)d_out : nxt;

        gru_kernel<<<(NN + TN - 1) / TN, 256, GRU_SMEM>>>(
            msum, cur,
            Wih + (size_t)ii * MSGD * 384, bih + (size_t)ii * 384,
            Whh + (size_t)ii * DD * 384,   bhh + (size_t)ii * 384,
            outp);

        if (step < 3) { float* t = cur; cur = nxt; nxt = t; }
    }
}

// round 8
// speedup vs baseline: 1.4038x; 1.2826x over previous
#include <cuda_runtime.h>
#include <math.h>

// Problem constants
#define NN   50000
#define DD   128
#define MM   800000
#define EE   32
#define KIN  160    // D + E
#define MSGD 128

// Edge kernel tiling: 64 edges/block, 128 threads, per-thread 16 rows x 4 cols
#define TE   64
#define EIS  160    // exact stride (reads are broadcast, writes conflict-free)
#define HS   256

// GRU kernel tiling
#define TN   32
#define XS   128
#define GS   384

typedef unsigned long long u64;

// Scratch (allocation-free rule: __device__ globals)
__device__ float g_msgsum[(size_t)NN * DD];
__device__ float g_bufA[(size_t)NN * DD];
__device__ float g_bufB[(size_t)NN * DD];

__device__ __forceinline__ float sigf(float x) { return 1.0f / (1.0f + expf(-x)); }

// ---- packed f32x2 helpers (bit-identical to 2x scalar FFMA) ----
__device__ __forceinline__ u64 pack2(float x) {
    u64 r;
    asm("mov.b64 %0, {%1, %1};" : "=l"(r) : "r"(__float_as_uint(x)));
    return r;
}
__device__ __forceinline__ void ffma2(u64& d, u64 a, u64 b) {
    asm("fma.rn.f32x2 %0, %1, %2, %0;" : "+l"(d) : "l"(a), "l"(b));
}
__device__ __forceinline__ void unpack2(u64 v, float& lo, float& hi) {
    unsigned int a, b;
    asm("mov.b64 {%0, %1}, %2;" : "=r"(a), "=r"(b) : "l"(v));
    lo = __uint_as_float(a); hi = __uint_as_float(b);
}

// ---------------------------------------------------------------------------
__global__ void copy_relu_kernel(const float* __restrict__ src, float* __restrict__ dst,
                                 int n, int do_relu) {
    int i = blockIdx.x * blockDim.x + threadIdx.x;
    if (i < n) {
        float v = src[i];
        dst[i] = do_relu ? fmaxf(v, 0.0f) : v;
    }
}

// ---------------------------------------------------------------------------
// Fused edge kernel. 64 edges/block (MM divisible by 64), 128 threads.
// Thread tile: 16 rows (rb = warp*16) x 4 cols (cb = lane*4).
// Weight LDG.128: 32 lanes cover a full 512B row -> 4 lines, no duplicates,
// L1-resident across warps/blocks. k-chunk=2 with double-buffered prefetch.
// ---------------------------------------------------------------------------
__global__ void __launch_bounds__(128, 2)
edge_kernel(const float* __restrict__ state,
            const int*   __restrict__ eidx,
            const float* __restrict__ efeat,
            const float* __restrict__ W1p, const float* __restrict__ b1p,
            const float* __restrict__ W2p, const float* __restrict__ b2p,
            const float* __restrict__ A1p, const float* __restrict__ ab1p,
            const float* __restrict__ A2p, const float* __restrict__ ab2p,
            float* __restrict__ msum)
{
    extern __shared__ float sm[];
    float* s_ei = sm;              // TE * EIS  (also reused as gate buffer later)
    float* s_h  = sm + TE * EIS;   // TE * HS
    __shared__ int s_src[TE];
    __shared__ int s_dst[TE];

    const int tid = threadIdx.x;
    const int m0  = blockIdx.x * TE;

    if (tid < TE) {
        s_src[tid] = eidx[m0 + tid];
        s_dst[tid] = eidx[MM + m0 + tid];
    }
    __syncthreads();

    // Gather diff part: 64 edges x 32 float4
    for (int t = tid; t < TE * 32; t += 128) {
        int e = t >> 5, q = t & 31;
        const float4 a = ((const float4*)(state + (size_t)s_src[e] * DD))[q];
        const float4 b = ((const float4*)(state + (size_t)s_dst[e] * DD))[q];
        float4 v; v.x = a.x - b.x; v.y = a.y - b.y; v.z = a.z - b.z; v.w = a.w - b.w;
        *(float4*)(s_ei + e * EIS + q * 4) = v;
    }
    // Edge features: 64 edges x 8 float4
    for (int t = tid; t < TE * 8; t += 128) {
        int e = t >> 3, q = t & 7;
        float4 v = ((const float4*)(efeat + (size_t)(m0 + e) * EE))[q];
        *(float4*)(s_ei + e * EIS + DD + q * 4) = v;
    }
    __syncthreads();

    const int lane = tid & 31;
    const int warp = tid >> 5;
    const int cb   = lane * 4;   // 4 cols per thread, 32 lanes cover 128 cols
    const int rb   = warp * 16;  // 16 rows per thread, 4 warps cover 64 rows

    // ---- GEMM1: H = relu(EI @ W + b), halves: 0 = msg net (W1), 1 = att net (A1)
    #pragma unroll
    for (int half = 0; half < 2; half++) {
        const float* Wp = half ? A1p : W1p;
        const float* bp = half ? ab1p : b1p;
        u64 acc[16][2];
        #pragma unroll
        for (int r = 0; r < 16; r++) { acc[r][0] = 0ull; acc[r][1] = 0ull; }

        ulonglong2 wa = *(const ulonglong2*)(Wp + 0 * MSGD + cb);
        ulonglong2 wb = *(const ulonglong2*)(Wp + 1 * MSGD + cb);
        for (int k0 = 0; k0 < KIN; k0 += 2) {
            int kn = (k0 + 2 < KIN) ? (k0 + 2) : 0;
            ulonglong2 na = *(const ulonglong2*)(Wp + kn * MSGD + cb);
            ulonglong2 nb = *(const ulonglong2*)(Wp + (kn + 1) * MSGD + cb);
            #pragma unroll
            for (int r = 0; r < 16; r++) {
                float2 e2 = *(const float2*)(s_ei + (rb + r) * EIS + k0);
                u64 p0 = pack2(e2.x);
                u64 p1 = pack2(e2.y);
                ffma2(acc[r][0], p0, wa.x);
                ffma2(acc[r][1], p0, wa.y);
                ffma2(acc[r][0], p1, wb.x);
                ffma2(acc[r][1], p1, wb.y);
            }
            wa = na; wb = nb;
        }
        const float4 bias = *(const float4*)(bp + cb);
        #pragma unroll
        for (int r = 0; r < 16; r++) {
            float v0, v1, v2, v3;
            unpack2(acc[r][0], v0, v1);
            unpack2(acc[r][1], v2, v3);
            float4 o;
            o.x = fmaxf(v0 + bias.x, 0.f);
            o.y = fmaxf(v1 + bias.y, 0.f);
            o.z = fmaxf(v2 + bias.z, 0.f);
            o.w = fmaxf(v3 + bias.w, 0.f);
            *(float4*)(s_h + (rb + r) * HS + half * MSGD + cb) = o;
        }
    }
    __syncthreads();
    // s_ei is dead now; reuse as per-thread gate buffer.

    // ---- GEMM2a: att = HA @ A2 + ab2 -> gate = sigmoid(att), stage in smem ----
    {
        u64 acc[16][2];
        #pragma unroll
        for (int r = 0; r < 16; r++) { acc[r][0] = 0ull; acc[r][1] = 0ull; }

        ulonglong2 wa = *(const ulonglong2*)(A2p + 0 * MSGD + cb);
        ulonglong2 wb = *(const ulonglong2*)(A2p + 1 * MSGD + cb);
        for (int k0 = 0; k0 < MSGD; k0 += 2) {
            int kn = (k0 + 2 < MSGD) ? (k0 + 2) : 0;
            ulonglong2 na = *(const ulonglong2*)(A2p + kn * MSGD + cb);
            ulonglong2 nb = *(const ulonglong2*)(A2p + (kn + 1) * MSGD + cb);
            #pragma unroll
            for (int r = 0; r < 16; r++) {
                float2 h2 = *(const float2*)(s_h + (rb + r) * HS + MSGD + k0);
                u64 p0 = pack2(h2.x);
                u64 p1 = pack2(h2.y);
                ffma2(acc[r][0], p0, wa.x);
                ffma2(acc[r][1], p0, wa.y);
                ffma2(acc[r][0], p1, wb.x);
                ffma2(acc[r][1], p1, wb.y);
            }
            wa = na; wb = nb;
        }
        const float4 ab = *(const float4*)(ab2p + cb);
        #pragma unroll
        for (int r = 0; r < 16; r++) {
            float a0, a1, a2, a3;
            unpack2(acc[r][0], a0, a1);
            unpack2(acc[r][1], a2, a3);
            float4 g;
            g.x = sigf(a0 + ab.x);
            g.y = sigf(a1 + ab.y);
            g.z = sigf(a2 + ab.z);
            g.w = sigf(a3 + ab.w);
            *(float4*)(s_ei + (rb + r) * EIS + cb) = g;  // thread-private reuse
        }
    }

    // ---- GEMM2b: msg = H1 @ W2 + b2; scatter msg*gate into msum ----
    {
        u64 acc[16][2];
        #pragma unroll
        for (int r = 0; r < 16; r++) { acc[r][0] = 0ull; acc[r][1] = 0ull; }

        ulonglong2 wa = *(const ulonglong2*)(W2p + 0 * MSGD + cb);
        ulonglong2 wb = *(const ulonglong2*)(W2p + 1 * MSGD + cb);
        for (int k0 = 0; k0 < MSGD; k0 += 2) {
            int kn = (k0 + 2 < MSGD) ? (k0 + 2) : 0;
            ulonglong2 na = *(const ulonglong2*)(W2p + kn * MSGD + cb);
            ulonglong2 nb = *(const ulonglong2*)(W2p + (kn + 1) * MSGD + cb);
            #pragma unroll
            for (int r = 0; r < 16; r++) {
                float2 h2 = *(const float2*)(s_h + (rb + r) * HS + k0);
                u64 p0 = pack2(h2.x);
                u64 p1 = pack2(h2.y);
                ffma2(acc[r][0], p0, wa.x);
                ffma2(acc[r][1], p0, wa.y);
                ffma2(acc[r][0], p1, wb.x);
                ffma2(acc[r][1], p1, wb.y);
            }
            wa = na; wb = nb;
        }
        const float4 b2v = *(const float4*)(b2p + cb);
        #pragma unroll
        for (int r = 0; r < 16; r++) {
            float m0v, m1v, m2v, m3v;
            unpack2(acc[r][0], m0v, m1v);
            unpack2(acc[r][1], m2v, m3v);
            float4 g = *(const float4*)(s_ei + (rb + r) * EIS + cb);
            float* dp = msum + (size_t)s_dst[rb + r] * DD + cb;
            atomicAdd(dp + 0, (m0v + b2v.x) * g.x);
            atomicAdd(dp + 1, (m1v + b2v.y) * g.y);
            atomicAdd(dp + 2, (m2v + b2v.z) * g.z);
            atomicAdd(dp + 3, (m3v + b2v.w) * g.w);
        }
    }
}

// ---------------------------------------------------------------------------
// Fused GRU kernel: per 32-node tile, 256 threads, f32x2 + weight prefetch.
// ---------------------------------------------------------------------------
__global__ void __launch_bounds__(256)
gru_kernel(const float* __restrict__ xmsg, const float* __restrict__ hstate,
           const float* __restrict__ Wih, const float* __restrict__ bih,
           const float* __restrict__ Whh, const float* __restrict__ bhh,
           float* __restrict__ out)
{
    extern __shared__ float sm[];
    float* s_x  = sm;                        // TN * XS
    float* s_h  = s_x + TN * XS;             // TN * XS
    float* s_gi = s_h + TN * XS;             // TN * GS
    float* s_gh = s_gi + TN * GS;            // TN * GS

    const int tid = threadIdx.x;
    const int n0  = blockIdx.x * TN;

    for (int t = tid; t < TN * 32; t += 256) {
        int r = t >> 5, q = t & 31;
        int node = n0 + r;
        float4 vx = make_float4(0.f, 0.f, 0.f, 0.f);
        float4 vh = vx;
        if (node < NN) {
            vx = ((const float4*)(xmsg   + (size_t)node * DD))[q];
            vh = ((const float4*)(hstate + (size_t)node * DD))[q];
        }
        *(float4*)(s_x + r * XS + q * 4) = vx;
        *(float4*)(s_h + r * XS + q * 4) = vh;
    }
    __syncthreads();

    const int lane = tid & 31;
    const int wg   = tid >> 5;     // 8 row groups
    const int rb   = wg * 4;
    const int cb   = lane * 12;    // 32*12 = 384 cols

    #pragma unroll
    for (int pass = 0; pass < 2; pass++) {
        const float* xs = pass ? s_h : s_x;
        const float* Wp = pass ? Whh : Wih;
        const float* bp = pass ? bhh : bih;
        float* gout     = pass ? s_gh : s_gi;

        u64 acc[4][6];
        #pragma unroll
        for (int i = 0; i < 4; i++)
            #pragma unroll
            for (int j = 0; j < 6; j++) acc[i][j] = 0ull;

        ulonglong2 w0a = *(const ulonglong2*)(Wp + 0 * 384 + cb);
        ulonglong2 w1a = *(const ulonglong2*)(Wp + 0 * 384 + cb + 4);
        ulonglong2 w2a = *(const ulonglong2*)(Wp + 0 * 384 + cb + 8);
        for (int k = 0; k < DD; k++) {
            int kn = (k + 1 < DD) ? (k + 1) : 0;
            ulonglong2 w0b = *(const ulonglong2*)(Wp + kn * 384 + cb);
            ulonglong2 w1b = *(const ulonglong2*)(Wp + kn * 384 + cb + 4);
            ulonglong2 w2b = *(const ulonglong2*)(Wp + kn * 384 + cb + 8);
            #pragma unroll
            for (int i = 0; i < 4; i++) {
                u64 xv = pack2(xs[(rb + i) * XS + k]);
                ffma2(acc[i][0], xv, w0a.x);
                ffma2(acc[i][1], xv, w0a.y);
                ffma2(acc[i][2], xv, w1a.x);
                ffma2(acc[i][3], xv, w1a.y);
                ffma2(acc[i][4], xv, w2a.x);
                ffma2(acc[i][5], xv, w2a.y);
            }
            w0a = w0b; w1a = w1b; w2a = w2b;
        }
        #pragma unroll
        for (int i = 0; i < 4; i++) {
            #pragma unroll
            for (int j = 0; j < 6; j++) {
                float lo, hi;
                unpack2(acc[i][j], lo, hi);
                gout[(rb + i) * GS + cb + 2 * j]     = lo + bp[cb + 2 * j];
                gout[(rb + i) * GS + cb + 2 * j + 1] = hi + bp[cb + 2 * j + 1];
            }
        }
        __syncthreads();
    }

    for (int t = tid; t < TN * DD; t += 256) {
        int r = t >> 7, j = t & 127;
        int node = n0 + r;
        if (node >= NN) continue;
        float gir = s_gi[r * GS + j];
        float giz = s_gi[r * GS + 128 + j];
        float gin = s_gi[r * GS + 256 + j];
        float ghr = s_gh[r * GS + j];
        float ghz = s_gh[r * GS + 128 + j];
        float ghn = s_gh[r * GS + 256 + j];
        float h   = s_h[r * XS + j];
        float rr  = sigf(gir + ghr);
        float zz  = sigf(giz + ghz);
        float nn  = tanhf(gin + rr * ghn);
        out[(size_t)node * DD + j] = (1.0f - zz) * nn + zz * h;
    }
}

// ---------------------------------------------------------------------------
extern "C" void kernel_launch(void* const* d_in, const int* in_sizes, int n_in,
                              void* d_out, int out_size) {
    const float* node_feat = (const float*)d_in[0];
    const int*   edge_index = (const int*)d_in[1];
    const float* edge_feat = (const float*)d_in[2];
    const float* W1  = (const float*)d_in[3];
    const float* b1  = (const float*)d_in[4];
    const float* W2  = (const float*)d_in[5];
    const float* b2  = (const float*)d_in[6];
    const float* A1  = (const float*)d_in[7];
    const float* ab1 = (const float*)d_in[8];
    const float* A2  = (const float*)d_in[9];
    const float* ab2 = (const float*)d_in[10];
    const float* Wih = (const float*)d_in[11];
    const float* bih = (const float*)d_in[12];
    const float* Whh = (const float*)d_in[13];
    const float* bhh = (const float*)d_in[14];

    float *msum, *bufA, *bufB;
    cudaGetSymbolAddress((void**)&msum, g_msgsum);
    cudaGetSymbolAddress((void**)&bufA, g_bufA);
    cudaGetSymbolAddress((void**)&bufB, g_bufB);

    const int EDGE_SMEM = (TE * EIS + TE * HS) * (int)sizeof(float);         // 104 KB
    const int GRU_SMEM  = (2 * TN * XS + 2 * TN * GS) * (int)sizeof(float);  // 128 KB
    cudaFuncSetAttribute(edge_kernel, cudaFuncAttributeMaxDynamicSharedMemorySize, EDGE_SMEM);
    cudaFuncSetAttribute(gru_kernel,  cudaFuncAttributeMaxDynamicSharedMemorySize, GRU_SMEM);

    const int nElems = NN * DD;

    copy_relu_kernel<<<(nElems + 255) / 256, 256>>>(node_feat, bufA, nElems, 0);

    float* cur = bufA;
    float* nxt = bufB;

    for (int step = 0; step < 4; step++) {
        int ii = step >> 1;

        if (step == 2) {
            copy_relu_kernel<<<(nElems + 255) / 256, 256>>>(cur, cur, nElems, 1);
        }

        cudaMemsetAsync(msum, 0, sizeof(float) * (size_t)nElems);

        edge_kernel<<<MM / TE, 128, EDGE_SMEM>>>(
            cur, edge_index, edge_feat,
            W1 + (size_t)ii * KIN * MSGD,  b1  + (size_t)ii * MSGD,
            W2 + (size_t)ii * MSGD * MSGD, b2  + (size_t)ii * MSGD,
            A1 + (size_t)ii * KIN * MSGD,  ab1 + (size_t)ii * MSGD,
            A2 + (size_t)ii * MSGD * MSGD, ab2 + (size_t)ii * MSGD,
            msum);

        float* outp = (step == 3) ? (float*)d_out : nxt;

        gru_kernel<<<(NN + TN - 1) / TN, 256, GRU_SMEM>>>(
            msum, cur,
            Wih + (size_t)ii * MSGD * 384, bih + (size_t)ii * 384,
            Whh + (size_t)ii * DD * 384,   bhh + (size_t)ii * 384,
            outp);

        if (step < 3) { float* t = cur; cur = nxt; nxt = t; }
    }
}